// round 13
// baseline (speedup 1.0000x reference)
#include <cuda_runtime.h>
#include <cuda_fp16.h>
#include <cstdint>

#define T_STEPS 512
#define BATCH   2048
#define IN_DIM  12
#define E_DIM   15
#define H_DIM   20
#define XS      (BATCH * IN_DIM)
#define OS      (BATCH * 3)
#define TCHUNKS 8
#define TPERC   (T_STEPS / TCHUNKS)   // 64
#define TPAD    (T_STEPS + 4)         // prefetch pad
#define RPS     (2 * H_DIM)           // row-pair stride in u64 per t (40)

typedef unsigned long long u64;
typedef uint32_t u32;

// Scratch: x-gate pre-activations as half4 (i,f,g,o) = one u64 per (b,t,cell).
// Pair-interleaved layout [b/2][t][cell][b&1] so the recurrence kernel fetches
// both rows of a pair with a single 16B load.
__device__ __align__(16) u64    g_xg[(size_t)(BATCH / 2) * TPAD * RPS];
__device__ __align__(16) u64    g_wcx[4][H_DIM][6];
__device__ __align__(16) float4 g_bc4[H_DIM];

__device__ __forceinline__ u64 pack2(float x, float y) {
    u64 u; asm("mov.b64 %0, {%1, %2};" : "=l"(u) : "f"(x), "f"(y)); return u;
}
__device__ __forceinline__ void unpack2(float& x, float& y, u64 u) {
    asm("mov.b64 {%0, %1}, %2;" : "=f"(x), "=f"(y) : "l"(u));
}
__device__ __forceinline__ u64 pack2u(u32 lo, u32 hi) {
    u64 u; asm("mov.b64 %0, {%1, %2};" : "=l"(u) : "r"(lo), "r"(hi)); return u;
}
__device__ __forceinline__ void unpack2u(u32& lo, u32& hi, u64 u) {
    asm("mov.b64 {%0, %1}, %2;" : "=r"(lo), "=r"(hi) : "l"(u));
}
__device__ __forceinline__ void fma2(u64& d, u64 a, u64 b) {
    asm("fma.rn.f32x2 %0, %1, %2, %0;" : "+l"(d) : "l"(a), "l"(b));
}
__device__ __forceinline__ float hsum2(u64 u) {
    float x, y; unpack2(x, y, u); return x + y;
}
__device__ __forceinline__ float tanh_a(float x) {
    float y; asm("tanh.approx.f32 %0, %1;" : "=f"(y) : "f"(x)); return y;
}
__device__ __forceinline__ float sig_a(float x) {
    return fmaf(0.5f, tanh_a(0.5f * x), 0.5f);
}
__device__ __forceinline__ u32 saddr(const void* p) {
    return (u32)__cvta_generic_to_shared(p);
}
__device__ __forceinline__ void lds2d(u64& a, u64& b, u32 addr) {
    asm volatile("ld.shared.v2.b64 {%0, %1}, [%2];" : "=l"(a), "=l"(b) : "r"(addr));
}
__device__ __forceinline__ void sts64d(u32 addr, u64 v) {
    asm volatile("st.shared.b64 [%0], %1;" :: "r"(addr), "l"(v));
}
__device__ __forceinline__ void ldg2(u64& a, u64& b, const void* p) {
    asm volatile("ld.global.v2.b64 {%0, %1}, [%2];" : "=l"(a), "=l"(b) : "l"(p));
}
__device__ __forceinline__ float2 h2f(u32 v) {
    __half2 h = *reinterpret_cast<__half2*>(&v);
    return __half22float2(h);
}

// ============ Kernel 0: fuse Wc = Wih@Wemb, bc once ============
__global__ void prep_kernel(const float* __restrict__ Wemb, const float* __restrict__ bemb,
                            const float* __restrict__ Wih,  const float* __restrict__ bih,
                            const float* __restrict__ bhh)
{
    const int tid = threadIdx.x;
    for (int i = tid; i < 480; i += blockDim.x) {
        const int g = i / 120, rem = i - g * 120;
        const int k = rem / 6, jj = rem - k * 6;
        const int r = g * H_DIM + k;
        float c0 = 0.f, c1 = 0.f;
#pragma unroll
        for (int e = 0; e < E_DIM; ++e) {
            const float wie = Wih[r * E_DIM + e];
            c0 += wie * Wemb[e * IN_DIM + 2 * jj];
            c1 += wie * Wemb[e * IN_DIM + 2 * jj + 1];
        }
        g_wcx[g][k][jj] = pack2(c0, c1);
    }
    if (tid < H_DIM) {
        float4 b4;
        float* bp = &b4.x;
#pragma unroll
        for (int g = 0; g < 4; ++g) {
            const int r = g * H_DIM + tid;
            float b = bih[r] + bhh[r];
#pragma unroll
            for (int e = 0; e < E_DIM; ++e) b += Wih[r * E_DIM + e] * bemb[e];
            bp[g] = b;
        }
        g_bc4[tid] = b4;
    }
}

// ============ Kernel 1: x-gate precompute -> half4 scratch ============
__global__ void __launch_bounds__(32, 16)
xgate_kernel(const float* __restrict__ X)
{
    const int lane = threadIdx.x;
    const int b    = blockIdx.x;
    const int tc   = blockIdx.y;
    const int k    = (lane < H_DIM) ? lane : 0;

    u64 wg[4][6];
#pragma unroll
    for (int g = 0; g < 4; ++g)
#pragma unroll
        for (int jj = 0; jj < 6; ++jj) wg[g][jj] = g_wcx[g][k][jj];
    const float4 b4 = g_bc4[k];

    const float* xp = X + (long long)(tc * TPERC) * XS + (long long)b * IN_DIM;
    u64* op = g_xg + ((size_t)(b >> 1) * TPAD + tc * TPERC) * RPS + 2 * k + (b & 1);

    u64 xa0, xa1, xa2, xa3, xa4, xa5;
    ldg2(xa0, xa1, xp); ldg2(xa2, xa3, xp + 4); ldg2(xa4, xa5, xp + 8);
    xp += XS;

#define XGBODY(X0, X1, X2, X3, X4, X5)                                          \
    do {                                                                        \
        u64 a0 = pack2(b4.x, 0.f), a1 = pack2(b4.y, 0.f);                       \
        u64 a2 = pack2(b4.z, 0.f), a3 = pack2(b4.w, 0.f);                       \
        fma2(a0, wg[0][0], X0); fma2(a1, wg[1][0], X0); fma2(a2, wg[2][0], X0); fma2(a3, wg[3][0], X0); \
        fma2(a0, wg[0][1], X1); fma2(a1, wg[1][1], X1); fma2(a2, wg[2][1], X1); fma2(a3, wg[3][1], X1); \
        fma2(a0, wg[0][2], X2); fma2(a1, wg[1][2], X2); fma2(a2, wg[2][2], X2); fma2(a3, wg[3][2], X2); \
        fma2(a0, wg[0][3], X3); fma2(a1, wg[1][3], X3); fma2(a2, wg[2][3], X3); fma2(a3, wg[3][3], X3); \
        fma2(a0, wg[0][4], X4); fma2(a1, wg[1][4], X4); fma2(a2, wg[2][4], X4); fma2(a3, wg[3][4], X4); \
        fma2(a0, wg[0][5], X5); fma2(a1, wg[1][5], X5); fma2(a2, wg[2][5], X5); fma2(a3, wg[3][5], X5); \
        __half2 hl = __floats2half2_rn(hsum2(a0), hsum2(a1));                   \
        __half2 hh = __floats2half2_rn(hsum2(a2), hsum2(a3));                   \
        const u64 v = pack2u(*reinterpret_cast<u32*>(&hl),                      \
                             *reinterpret_cast<u32*>(&hh));                     \
        if (lane < H_DIM) *op = v;                                              \
        op += RPS;                                                              \
    } while (0)

#pragma unroll 1
    for (int it = 0; it < TPERC; it += 2) {
        u64 xb0, xb1, xb2, xb3, xb4, xb5;
        ldg2(xb0, xb1, xp); ldg2(xb2, xb3, xp + 4); ldg2(xb4, xb5, xp + 8);
        xp += XS;
        XGBODY(xa0, xa1, xa2, xa3, xa4, xa5);
        ldg2(xa0, xa1, xp); ldg2(xa2, xa3, xp + 4); ldg2(xa4, xa5, xp + 8);
        xp += XS;
        XGBODY(xb0, xb1, xb2, xb3, xb4, xb5);
    }
#undef XGBODY
}

// ============ Kernel 2: recurrence, 2 rows per warp ============
__global__ void __launch_bounds__(32, 7)
lstm_kernel(const float* __restrict__ Whh,
            const float* __restrict__ Wout, const float* __restrict__ bout,
            float* __restrict__ out)
{
    __shared__ __align__(16) u64 hdA[2][H_DIM];   // row A (h,h) pairs, ping-pong
    __shared__ __align__(16) u64 hdB[2][H_DIM];   // row B

    const int lane = threadIdx.x;
    const int b2   = blockIdx.x;                  // rows 2*b2, 2*b2+1
    const bool hL  = lane < H_DIM;
    const bool oL  = (lane >= H_DIM) && (lane < H_DIM + 6);
    const int rowB = (lane >= H_DIM + 3) ? 1 : 0;
    const int m    = oL ? (lane - H_DIM - 3 * rowB) : 0;
    const int k    = hL ? lane : 0;

    u64 w01[H_DIM], w23[H_DIM];
    u64 bO = 0ull;
    if (hL) {
#pragma unroll
        for (int j = 0; j < H_DIM; ++j) {
            w01[j] = pack2(Whh[lane * H_DIM + j],               Whh[(H_DIM + lane) * H_DIM + j]);
            w23[j] = pack2(Whh[(2 * H_DIM + lane) * H_DIM + j], Whh[(3 * H_DIM + lane) * H_DIM + j]);
        }
    } else {
#pragma unroll
        for (int j = 0; j < H_DIM; ++j) { w01[j] = 0ull; w23[j] = 0ull; }
        if (oL) {
#pragma unroll
            for (int j = 0; j < H_DIM; ++j) w01[j] = pack2(Wout[m * H_DIM + j], 0.f);
            bO = pack2(bout[m], 0.f);
        }
    }
    if (hL) { hdA[0][lane] = 0ull; hdB[0][lane] = 0ull; }
    __syncwarp();

    const u32 a0A = saddr(&hdA[0][0]);
    const u32 a1A = saddr(&hdA[1][0]);
    const u32 a0B = saddr(&hdB[0][0]);
    const u32 a1B = saddr(&hdB[1][0]);
    const u32 wA0 = a0A + lane * 8, wA1 = a1A + lane * 8;
    const u32 wB0 = a0B + lane * 8, wB1 = a1B + lane * 8;

    const u64* gp = g_xg + (size_t)b2 * TPAD * RPS + 2 * k;
    u64 pa0, pa1, pb0, pb1, pc0, pc1, pd0, pd1;
    ldg2(pa0, pa1, gp);
    ldg2(pb0, pb1, gp + RPS);
    ldg2(pc0, pc1, gp + 2 * RPS);
    ldg2(pd0, pd1, gp + 3 * RPS);
    gp += 4 * RPS;

    float cA = 0.f, cB = 0.f;
    const int grow = 2 * b2 + rowB;
    float* outp = out + (long long)grow * 3 + m - OS;

#define STEP(PXA, PXB, HRA, HRB, HWA, HWB, DOOUT)                              \
    do {                                                                       \
        u32 xl, xh;                                                            \
        unpack2u(xl, xh, (PXA));                                               \
        const float2 lA = h2f(xl), hA = h2f(xh);                               \
        u64 aA01 = hL ? pack2(lA.x, lA.y) : bO;                                \
        u64 aA23 = pack2(hA.x, hA.y);                                          \
        unpack2u(xl, xh, (PXB));                                               \
        const float2 lB = h2f(xl), hB = h2f(xh);                               \
        u64 aB01 = hL ? pack2(lB.x, lB.y) : bO;                                \
        u64 aB23 = pack2(hB.x, hB.y);                                          \
        u64 e0, e1, e2, e3, f0, f1, f2, f3;                                    \
        _Pragma("unroll")                                                      \
        for (int q = 0; q < 5; ++q) {                                          \
            lds2d(e0, e1, (HRA) + q * 32); lds2d(e2, e3, (HRA) + q * 32 + 16); \
            lds2d(f0, f1, (HRB) + q * 32); lds2d(f2, f3, (HRB) + q * 32 + 16); \
            fma2(aA01, w01[4 * q],     e0); fma2(aA23, w23[4 * q],     e0);    \
            fma2(aB01, w01[4 * q],     f0); fma2(aB23, w23[4 * q],     f0);    \
            fma2(aA01, w01[4 * q + 1], e1); fma2(aA23, w23[4 * q + 1], e1);    \
            fma2(aB01, w01[4 * q + 1], f1); fma2(aB23, w23[4 * q + 1], f1);    \
            fma2(aA01, w01[4 * q + 2], e2); fma2(aA23, w23[4 * q + 2], e2);    \
            fma2(aB01, w01[4 * q + 2], f2); fma2(aB23, w23[4 * q + 2], f2);    \
            fma2(aA01, w01[4 * q + 3], e3); fma2(aA23, w23[4 * q + 3], e3);    \
            fma2(aB01, w01[4 * q + 3], f3); fma2(aB23, w23[4 * q + 3], f3);    \
        }                                                                      \
        float p0, p1, p2, p3, q0, q1, q2, q3;                                  \
        unpack2(p0, p1, aA01); unpack2(p2, p3, aA23);                          \
        unpack2(q0, q1, aB01); unpack2(q2, q3, aB23);                          \
        const float ivA = sig_a(p0), fvA = sig_a(p1);                          \
        const float gvA = tanh_a(p2), ovA = sig_a(p3);                         \
        const float ivB = sig_a(q0), fvB = sig_a(q1);                          \
        const float gvB = tanh_a(q2), ovB = sig_a(q3);                         \
        cA = fmaf(fvA, cA, ivA * gvA);                                         \
        cB = fmaf(fvB, cB, ivB * gvB);                                         \
        const float hAo = ovA * tanh_a(cA);                                    \
        const float hBo = ovB * tanh_a(cB);                                    \
        if (hL) { sts64d((HWA), pack2(hAo, hAo));                              \
                  sts64d((HWB), pack2(hBo, hBo)); }                            \
        if (oL && (DOOUT)) *outp = rowB ? q0 : p0;                             \
        outp += OS;                                                            \
        ldg2((PXA), (PXB), gp); gp += RPS;                                     \
        __syncwarp();                                                          \
    } while (0)

    STEP(pa0, pa1, a0A, a0B, wA1, wB1, false);
    STEP(pb0, pb1, a1A, a1B, wA0, wB0, true);
    STEP(pc0, pc1, a0A, a0B, wA1, wB1, true);
    STEP(pd0, pd1, a1A, a1B, wA0, wB0, true);
#pragma unroll 1
    for (int t4 = 4; t4 < T_STEPS; t4 += 4) {
        STEP(pa0, pa1, a0A, a0B, wA1, wB1, true);
        STEP(pb0, pb1, a1A, a1B, wA0, wB0, true);
        STEP(pc0, pc1, a0A, a0B, wA1, wB1, true);
        STEP(pd0, pd1, a1A, a1B, wA0, wB0, true);
    }
#undef STEP

    // final out[T-1]: h_511 lives in buf 0 for both rows
    {
        u64 aA = bO, aB = bO;
        u64 e0, e1, e2, e3, f0, f1, f2, f3;
#pragma unroll
        for (int q = 0; q < 5; ++q) {
            lds2d(e0, e1, a0A + q * 32); lds2d(e2, e3, a0A + q * 32 + 16);
            lds2d(f0, f1, a0B + q * 32); lds2d(f2, f3, a0B + q * 32 + 16);
            fma2(aA, w01[4 * q],     e0); fma2(aB, w01[4 * q],     f0);
            fma2(aA, w01[4 * q + 1], e1); fma2(aB, w01[4 * q + 1], f1);
            fma2(aA, w01[4 * q + 2], e2); fma2(aB, w01[4 * q + 2], f2);
            fma2(aA, w01[4 * q + 3], e3); fma2(aB, w01[4 * q + 3], f3);
        }
        if (oL) {
            float v, d;
            if (rowB) unpack2(v, d, aB); else unpack2(v, d, aA);
            *outp = v;
        }
    }
}

extern "C" void kernel_launch(void* const* d_in, const int* in_sizes, int n_in,
                              void* d_out, int out_size) {
    const float* X    = (const float*)d_in[0];
    const float* Wemb = (const float*)d_in[1];
    const float* bemb = (const float*)d_in[2];
    const float* Wih  = (const float*)d_in[3];
    const float* bih  = (const float*)d_in[4];
    const float* Whh  = (const float*)d_in[5];
    const float* bhh  = (const float*)d_in[6];
    const float* Wout = (const float*)d_in[7];
    const float* bout = (const float*)d_in[8];
    float* out = (float*)d_out;

    prep_kernel<<<1, 256>>>(Wemb, bemb, Wih, bih, bhh);
    dim3 g1(BATCH, TCHUNKS);
    xgate_kernel<<<g1, 32>>>(X);
    lstm_kernel<<<BATCH / 2, 32>>>(Whh, Wout, bout, out);
}